// round 1
// baseline (speedup 1.0000x reference)
#include <cuda_runtime.h>

// ---------------- problem constants ----------------
constexpr int  B_    = 16;
constexpr int  N_    = 1024;
constexpr int  CIN   = 768;
constexpr int  H_    = 8;
constexpr int  KQ_   = 256;
constexpr int  VD_   = 512;
constexpr long MTOK  = (long)B_ * N_;              // 16384
constexpr long QKVC  = 2L * H_ * KQ_ + (long)H_ * VD_; // 8192
constexpr long NHV   = (long)H_ * VD_;             // 4096
constexpr int  DOUT  = 512;
constexpr float SCALE_ = 0.04419417382415922f;     // 512^-0.5
constexpr float EPS_   = 1e-5f;

// ---------------- scratch (device globals; no allocation allowed) ----------------
__device__ float g_qkv [MTOK * QKVC];                      // 512 MB
__device__ float g_attn[(long)B_ * H_ * N_ * N_];          // 536 MB
__device__ float g_ao  [MTOK * NHV];                       // 268 MB
__device__ float g_qs[QKVC], g_qh[QKVC];
__device__ float g_ps[DOUT], g_ph[DOUT];

// ---------------- BN param folding ----------------
__global__ void bn_prep_kernel(const float* __restrict__ g, const float* __restrict__ b,
                               const float* __restrict__ mu, const float* __restrict__ var,
                               float* __restrict__ sc, float* __restrict__ sh, int n) {
    int i = blockIdx.x * blockDim.x + threadIdx.x;
    if (i < n) {
        float s = g[i] * rsqrtf(var[i] + EPS_);
        sc[i] = s;
        sh[i] = b[i] - mu[i] * s;
    }
}

// ---------------- generic 128x128x16 fp32 GEMM, C = A * op(B), fused epilogues --------
// BT=true : B stored [N][K], K contiguous (i.e. C = A * B^T with both row-major)
// BT=false: B stored [K][N], N contiguous
// MODE 0: out = acc*scale[n] + shift[n]          (BN)
// MODE 1: out = acc*alpha + bias[(z%zdiv)*bias_is + row*ldbias + col]  (attn logits)
// MODE 2: out = clamp(acc, -1, 1)                (Hardtanh)
// All dims must divide (128,128,16) -- true for every GEMM in this problem.
template<bool BT, int MODE>
__global__ __launch_bounds__(256, 2)
void gemm128_kernel(const float* __restrict__ Aall, long lda, long aos, long ais,
                    const float* __restrict__ Ball, long ldb, long bos, long bis,
                    float* __restrict__ Call, long ldc, long cos_, long cis,
                    int K, int zdiv,
                    const float* __restrict__ p0, const float* __restrict__ p1,
                    float alpha, long bias_is, long ldbias)
{
    const int z  = blockIdx.z;
    const int zo = z / zdiv, zi = z - zo * zdiv;
    const float* A  = Aall + (long)zo * aos + (long)zi * ais;
    const float* Bp = Ball + (long)zo * bos + (long)zi * bis;
    float*       C  = Call + (long)zo * cos_ + (long)zi * cis;
    const long m0 = (long)blockIdx.y * 128;
    const long n0 = (long)blockIdx.x * 128;

    __shared__ float As[16][132];
    __shared__ float Bs[16][132];

    const int tid  = threadIdx.x;
    const int lrow = tid >> 2;            // 0..63
    const int lk4  = (tid & 3) << 2;      // 0,4,8,12
    const int krow = tid >> 5;            // 0..7
    const int nq   = (tid & 31) << 2;     // 0..124
    const int tx   = tid & 15, ty = tid >> 4;
    const int mreg = ty << 3, nreg = tx << 3;

    float acc[8][8];
#pragma unroll
    for (int i = 0; i < 8; i++)
#pragma unroll
        for (int j = 0; j < 8; j++) acc[i][j] = 0.f;

    for (int k0 = 0; k0 < K; k0 += 16) {
#pragma unroll
        for (int p = 0; p < 2; p++) {
            int r = lrow + p * 64;
            const float4 av = *(const float4*)(A + (m0 + r) * lda + k0 + lk4);
            As[lk4 + 0][r] = av.x; As[lk4 + 1][r] = av.y;
            As[lk4 + 2][r] = av.z; As[lk4 + 3][r] = av.w;
        }
        if (BT) {
#pragma unroll
            for (int p = 0; p < 2; p++) {
                int r = lrow + p * 64;
                const float4 bv = *(const float4*)(Bp + (n0 + r) * ldb + k0 + lk4);
                Bs[lk4 + 0][r] = bv.x; Bs[lk4 + 1][r] = bv.y;
                Bs[lk4 + 2][r] = bv.z; Bs[lk4 + 3][r] = bv.w;
            }
        } else {
#pragma unroll
            for (int p = 0; p < 2; p++) {
                int kr = krow + p * 8;
                const float4 bv = *(const float4*)(Bp + (long)(k0 + kr) * ldb + n0 + nq);
                *(float4*)&Bs[kr][nq] = bv;
            }
        }
        __syncthreads();
#pragma unroll
        for (int kk = 0; kk < 16; kk++) {
            float af[8], bf[8];
            *(float4*)&af[0] = *(const float4*)&As[kk][mreg];
            *(float4*)&af[4] = *(const float4*)&As[kk][mreg + 4];
            *(float4*)&bf[0] = *(const float4*)&Bs[kk][nreg];
            *(float4*)&bf[4] = *(const float4*)&Bs[kk][nreg + 4];
#pragma unroll
            for (int i = 0; i < 8; i++)
#pragma unroll
                for (int j = 0; j < 8; j++)
                    acc[i][j] = fmaf(af[i], bf[j], acc[i][j]);
        }
        __syncthreads();
    }

    // -------- epilogue --------
    if (MODE == 0) {
        float sv[8], sh[8];
#pragma unroll
        for (int j = 0; j < 8; j++) { sv[j] = p0[n0 + nreg + j]; sh[j] = p1[n0 + nreg + j]; }
#pragma unroll
        for (int i = 0; i < 8; i++) {
            long row = m0 + mreg + i;
            float4 o0, o1;
            o0.x = fmaf(acc[i][0], sv[0], sh[0]); o0.y = fmaf(acc[i][1], sv[1], sh[1]);
            o0.z = fmaf(acc[i][2], sv[2], sh[2]); o0.w = fmaf(acc[i][3], sv[3], sh[3]);
            o1.x = fmaf(acc[i][4], sv[4], sh[4]); o1.y = fmaf(acc[i][5], sv[5], sh[5]);
            o1.z = fmaf(acc[i][6], sv[6], sh[6]); o1.w = fmaf(acc[i][7], sv[7], sh[7]);
            *(float4*)(C + row * ldc + n0 + nreg)     = o0;
            *(float4*)(C + row * ldc + n0 + nreg + 4) = o1;
        }
    } else if (MODE == 1) {
        const float* bias = p0 + (long)zi * bias_is;
#pragma unroll
        for (int i = 0; i < 8; i++) {
            long row = m0 + mreg + i;
            const float4 b0 = *(const float4*)(bias + row * ldbias + n0 + nreg);
            const float4 b1 = *(const float4*)(bias + row * ldbias + n0 + nreg + 4);
            float4 o0, o1;
            o0.x = fmaf(acc[i][0], alpha, b0.x); o0.y = fmaf(acc[i][1], alpha, b0.y);
            o0.z = fmaf(acc[i][2], alpha, b0.z); o0.w = fmaf(acc[i][3], alpha, b0.w);
            o1.x = fmaf(acc[i][4], alpha, b1.x); o1.y = fmaf(acc[i][5], alpha, b1.y);
            o1.z = fmaf(acc[i][6], alpha, b1.z); o1.w = fmaf(acc[i][7], alpha, b1.w);
            *(float4*)(C + row * ldc + n0 + nreg)     = o0;
            *(float4*)(C + row * ldc + n0 + nreg + 4) = o1;
        }
    } else {
#pragma unroll
        for (int i = 0; i < 8; i++) {
            long row = m0 + mreg + i;
            float4 o0, o1;
            o0.x = fminf(fmaxf(acc[i][0], -1.f), 1.f); o0.y = fminf(fmaxf(acc[i][1], -1.f), 1.f);
            o0.z = fminf(fmaxf(acc[i][2], -1.f), 1.f); o0.w = fminf(fmaxf(acc[i][3], -1.f), 1.f);
            o1.x = fminf(fmaxf(acc[i][4], -1.f), 1.f); o1.y = fminf(fmaxf(acc[i][5], -1.f), 1.f);
            o1.z = fminf(fmaxf(acc[i][6], -1.f), 1.f); o1.w = fminf(fmaxf(acc[i][7], -1.f), 1.f);
            *(float4*)(C + row * ldc + n0 + nreg)     = o0;
            *(float4*)(C + row * ldc + n0 + nreg + 4) = o1;
        }
    }
}

// ---------------- rowwise softmax over 1024 elements ----------------
__global__ void softmax1024_kernel(float* __restrict__ attn) {
    float* p = attn + (long)blockIdx.x * 1024;
    const int t = threadIdx.x;  // 128 threads, 8 elems each
    float4 a = ((const float4*)p)[t];
    float4 b = ((const float4*)p)[t + 128];

    float m = fmaxf(fmaxf(fmaxf(a.x, a.y), fmaxf(a.z, a.w)),
                    fmaxf(fmaxf(b.x, b.y), fmaxf(b.z, b.w)));
#pragma unroll
    for (int o = 16; o > 0; o >>= 1) m = fmaxf(m, __shfl_xor_sync(0xffffffffu, m, o));
    __shared__ float sm[4], ss[4];
    if ((t & 31) == 0) sm[t >> 5] = m;
    __syncthreads();
    m = fmaxf(fmaxf(sm[0], sm[1]), fmaxf(sm[2], sm[3]));

    a.x = __expf(a.x - m); a.y = __expf(a.y - m); a.z = __expf(a.z - m); a.w = __expf(a.w - m);
    b.x = __expf(b.x - m); b.y = __expf(b.y - m); b.z = __expf(b.z - m); b.w = __expf(b.w - m);

    float s = a.x + a.y + a.z + a.w + b.x + b.y + b.z + b.w;
#pragma unroll
    for (int o = 16; o > 0; o >>= 1) s += __shfl_xor_sync(0xffffffffu, s, o);
    if ((t & 31) == 0) ss[t >> 5] = s;
    __syncthreads();
    s = ss[0] + ss[1] + ss[2] + ss[3];
    const float inv = 1.0f / s;

    a.x *= inv; a.y *= inv; a.z *= inv; a.w *= inv;
    b.x *= inv; b.y *= inv; b.z *= inv; b.w *= inv;
    ((float4*)p)[t] = a;
    ((float4*)p)[t + 128] = b;
}

// ---------------- launch ----------------
extern "C" void kernel_launch(void* const* d_in, const int* in_sizes, int n_in,
                              void* d_out, int out_size) {
    const float* x          = (const float*)d_in[0];
    const float* qkv_w      = (const float*)d_in[1];
    const float* qkv_gamma  = (const float*)d_in[2];
    const float* qkv_beta   = (const float*)d_in[3];
    const float* qkv_mean   = (const float*)d_in[4];
    const float* qkv_var    = (const float*)d_in[5];
    const float* pos_bias   = (const float*)d_in[6];
    const float* proj_w     = (const float*)d_in[7];
    const float* proj_gamma = (const float*)d_in[8];
    const float* proj_beta  = (const float*)d_in[9];
    const float* proj_mean  = (const float*)d_in[10];
    const float* proj_var   = (const float*)d_in[11];
    float* out = (float*)d_out;

    float *qkv, *attn, *ao, *qs, *qh, *ps, *ph;
    cudaGetSymbolAddress((void**)&qkv,  g_qkv);
    cudaGetSymbolAddress((void**)&attn, g_attn);
    cudaGetSymbolAddress((void**)&ao,   g_ao);
    cudaGetSymbolAddress((void**)&qs,   g_qs);
    cudaGetSymbolAddress((void**)&qh,   g_qh);
    cudaGetSymbolAddress((void**)&ps,   g_ps);
    cudaGetSymbolAddress((void**)&ph,   g_ph);

    const dim3 blk(256);

    // fold BN params
    bn_prep_kernel<<<(int)((QKVC + 255) / 256), 256>>>(qkv_gamma, qkv_beta, qkv_mean, qkv_var, qs, qh, (int)QKVC);
    bn_prep_kernel<<<(DOUT + 255) / 256, 256>>>(proj_gamma, proj_beta, proj_mean, proj_var, ps, ph, DOUT);

    // 1) qkv = BN(x @ qkv_w^T)   [16384 x 8192], K=768
    gemm128_kernel<true, 0><<<dim3(QKVC / 128, MTOK / 128, 1), blk>>>(
        x, CIN, 0, 0,
        qkv_w, CIN, 0, 0,
        qkv, QKVC, 0, 0,
        CIN, 1, qs, qh, 0.f, 0, 0);

    // 2) logits[z=b*8+h] = q @ k^T * SCALE + pos_bias[h]   [1024 x 1024], K=256
    const long perB = (long)N_ * QKVC;     // 8388608
    const long NN   = (long)N_ * N_;       // 1048576
    gemm128_kernel<true, 1><<<dim3(8, 8, B_ * H_), blk>>>(
        qkv,        QKVC, perB, 1024,      // q : + h*1024
        qkv + 256,  QKVC, perB, 1024,      // k : + h*1024 + 256
        attn, N_, 8 * NN, NN,
        KQ_, H_, pos_bias, nullptr, SCALE_, NN, N_);

    // 3) softmax rows
    softmax1024_kernel<<<(unsigned)(B_ * H_ * N_), 128>>>(attn);

    // 4) ao = clip(attn @ v)   per (b,h): [1024 x 512], K=1024 ; write [b,n,h*512+d]
    gemm128_kernel<false, 2><<<dim3(4, 8, B_ * H_), blk>>>(
        attn, N_, 8 * NN, NN,
        qkv + 512, QKVC, perB, 1024,       // v rows: stride 8192, d contiguous
        ao, NHV, (long)N_ * NHV, VD_,
        N_, H_, nullptr, nullptr, 0.f, 0, 0);

    // 5) out = BN(ao @ proj_w^T)   [16384 x 512], K=4096
    gemm128_kernel<true, 0><<<dim3(DOUT / 128, MTOK / 128, 1), blk>>>(
        ao, NHV, 0, 0,
        proj_w, NHV, 0, 0,
        out, DOUT, 0, 0,
        (int)NHV, 1, ps, ph, 0.f, 0, 0);
}

// round 3
// speedup vs baseline: 3.1265x; 3.1265x over previous
#include <cuda_runtime.h>
#include <cstdint>

// ---------------- problem constants ----------------
constexpr int  B_    = 16;
constexpr int  N_    = 1024;
constexpr int  CIN   = 768;
constexpr int  H_    = 8;
constexpr int  KQ_   = 256;
constexpr int  VD_   = 512;
constexpr long MTOK  = 16384;
constexpr long QKVC  = 8192;
constexpr long NHV   = 4096;
constexpr int  DOUT  = 512;
constexpr float SCALE_ = 0.04419417382415922f;     // 512^-0.5
constexpr float EPS_   = 1e-5f;

// ---------------- scratch (device globals) ----------------
__device__ float g_qkv [MTOK * QKVC];                      // 512 MB
__device__ float g_attn[(long)B_ * H_ * N_ * N_];          // 536 MB
__device__ float g_ao  [MTOK * NHV];                       // 268 MB
__device__ float g_vt  [(long)B_ * H_ * VD_ * N_];         // 256 MB
__device__ float g_xr  [MTOK * CIN];                       // 48 MB  (tf32-rounded x)
__device__ float g_wr  [QKVC * CIN];                       // 25 MB  (tf32-rounded qkv_w)
__device__ float g_pwr [(long)DOUT * NHV];                 // 8 MB   (tf32-rounded proj_w)
__device__ float g_qs[QKVC], g_qh[QKVC];
__device__ float g_ps[DOUT], g_ph[DOUT];

// ---------------- helpers ----------------
__device__ __forceinline__ float to_tf32(float x) {
    uint32_t u;
    asm("cvt.rna.tf32.f32 %0, %1;" : "=r"(u) : "f"(x));
    return __uint_as_float(u);
}
__device__ __forceinline__ void cp16(uint32_t s, const float* g) {
    asm volatile("cp.async.cg.shared.global [%0], [%1], 16;"
                 :: "r"(s), "l"(__cvta_generic_to_global(g)));
}
__device__ __forceinline__ uint32_t smem_u32(const void* p) {
    uint32_t a;
    asm("{ .reg .u64 t; cvta.to.shared.u64 t, %1; cvt.u32.u64 %0, t; }" : "=r"(a) : "l"(p));
    return a;
}
__device__ __forceinline__ void mma_tf32(float* c, const uint32_t* a, const uint32_t* b) {
    asm volatile(
        "mma.sync.aligned.m16n8k8.row.col.f32.tf32.tf32.f32 "
        "{%0,%1,%2,%3}, {%4,%5,%6,%7}, {%8,%9}, {%0,%1,%2,%3};"
        : "+f"(c[0]), "+f"(c[1]), "+f"(c[2]), "+f"(c[3])
        : "r"(a[0]), "r"(a[1]), "r"(a[2]), "r"(a[3]), "r"(b[0]), "r"(b[1]));
}

// ---------------- mma.sync tf32 GEMM: tile 128x128x32, C = A * B^T, fused epilogue -----
// A: [M][K] K-contig (tf32-rounded). B: [N][K] K-contig (tf32-rounded).
// MODE 0: round(BN)   1: alpha*acc + bias   2: round(clamp(-1,1))   3: BN (no round)
constexpr int LDT = 36;                 // padded smem row (floats) -> conflict-free frags
constexpr int CH  = 128 * LDT;          // floats per tile buffer (4608)
constexpr int SMEM_BYTES = 4 * CH * 4;  // 73728 B

template<int MODE>
__global__ __launch_bounds__(256)
void mma_gemm_kernel(const float* __restrict__ Aall, long lda, long aos, long ais,
                     const float* __restrict__ Ball, long ldb, long bos, long bis,
                     float* __restrict__ Call, long ldc, long cosz, long cis,
                     int K, int zdiv,
                     const float* __restrict__ p0, const float* __restrict__ p1,
                     float alpha, long bias_is, long ldbias)
{
    extern __shared__ float sm[];       // [A0][A1][B0][B1], each CH floats
    const uint32_t sbase = smem_u32(sm);

    const int tid = threadIdx.x;
    const int wid = tid >> 5, lane = tid & 31;
    const int wm = wid & 1, wn = wid >> 1;          // 2 x 4 warp grid
    const int rg = lane >> 2, lg = lane & 3;

    const int z  = blockIdx.z;
    const int zo = z / zdiv, zi = z - zo * zdiv;
    const float* A  = Aall + (long)zo * aos + (long)zi * ais;
    const float* Bp = Ball + (long)zo * bos + (long)zi * bis;
    float*       C  = Call + (long)zo * cosz + (long)zi * cis;
    const long m0 = (long)blockIdx.y * 128;
    const long n0 = (long)blockIdx.x * 128;

    // per-thread gmem source coords for the 4 float4s of each tile
    const int r_ld = tid >> 3;            // base row (0..31), +32 per rep? no: idx layout below
    float acc[4][4][4];
#pragma unroll
    for (int i = 0; i < 4; i++)
#pragma unroll
        for (int j = 0; j < 4; j++)
#pragma unroll
            for (int q = 0; q < 4; q++) acc[i][j][q] = 0.f;

    auto load_tile = [&](const float* src, long ld, int kc, int bufFloatOff) {
        const float* s = src + (long)kc * 32;
#pragma unroll
        for (int i = 0; i < 4; i++) {
            int idx = tid + i * 256;             // 0..1023
            int r = idx >> 3, c = idx & 7;       // row 0..127, float4 col 0..7
            cp16(sbase + (uint32_t)(r * LDT + c * 4) * 4u + (uint32_t)bufFloatOff * 4u,
                 s + (long)r * ld + c * 4);
        }
    };

    const float* Abase = A + m0 * lda;
    const float* Bbase = Bp + n0 * ldb;

    const int nch = K >> 5;
    load_tile(Abase, lda, 0, 0);
    load_tile(Bbase, ldb, 0, 2 * CH);
    asm volatile("cp.async.commit_group;");

    for (int kc = 0; kc < nch; kc++) {
        const int p = kc & 1;
        if (kc + 1 < nch) {
            load_tile(Abase, lda, kc + 1, (p ^ 1) * CH);
            load_tile(Bbase, ldb, kc + 1, 2 * CH + (p ^ 1) * CH);
            asm volatile("cp.async.commit_group;");
            asm volatile("cp.async.wait_group 1;");
        } else {
            asm volatile("cp.async.wait_group 0;");
        }
        __syncthreads();

        const float* as = sm + p * CH + (wm * 64 + rg) * LDT + lg;
        const float* bs = sm + 2 * CH + p * CH + (wn * 32 + rg) * LDT + lg;
#pragma unroll
        for (int ks = 0; ks < 4; ks++) {
            uint32_t a[4][4], b[4][2];
#pragma unroll
            for (int i = 0; i < 4; i++) {
                const float* ap = as + i * (16 * LDT) + ks * 8;
                a[i][0] = __float_as_uint(ap[0]);
                a[i][1] = __float_as_uint(ap[8 * LDT]);
                a[i][2] = __float_as_uint(ap[4]);
                a[i][3] = __float_as_uint(ap[8 * LDT + 4]);
            }
#pragma unroll
            for (int j = 0; j < 4; j++) {
                const float* bp = bs + j * (8 * LDT) + ks * 8;
                b[j][0] = __float_as_uint(bp[0]);
                b[j][1] = __float_as_uint(bp[4]);
            }
#pragma unroll
            for (int i = 0; i < 4; i++)
#pragma unroll
                for (int j = 0; j < 4; j++)
                    mma_tf32(acc[i][j], a[i], b[j]);
        }
        __syncthreads();
    }

    // -------- epilogue --------
    const long cr0 = m0 + wm * 64 + rg;
    const long cn0 = n0 + wn * 32 + 2 * lg;
#pragma unroll
    for (int i = 0; i < 4; i++) {
        const long r0 = cr0 + i * 16, r1 = r0 + 8;
#pragma unroll
        for (int j = 0; j < 4; j++) {
            const long cc = cn0 + j * 8;
            float v0 = acc[i][j][0], v1 = acc[i][j][1];
            float v2 = acc[i][j][2], v3 = acc[i][j][3];
            if (MODE == 0 || MODE == 3) {
                const float s0 = p0[cc], s1 = p0[cc + 1];
                const float h0 = p1[cc], h1 = p1[cc + 1];
                v0 = fmaf(v0, s0, h0); v1 = fmaf(v1, s1, h1);
                v2 = fmaf(v2, s0, h0); v3 = fmaf(v3, s1, h1);
                if (MODE == 0) { v0 = to_tf32(v0); v1 = to_tf32(v1); v2 = to_tf32(v2); v3 = to_tf32(v3); }
            } else if (MODE == 1) {
                const float* bias = p0 + (long)zi * bias_is;
                const float2 b0 = *(const float2*)(bias + r0 * ldbias + cc);
                const float2 b1 = *(const float2*)(bias + r1 * ldbias + cc);
                v0 = fmaf(v0, alpha, b0.x); v1 = fmaf(v1, alpha, b0.y);
                v2 = fmaf(v2, alpha, b1.x); v3 = fmaf(v3, alpha, b1.y);
            } else {
                v0 = to_tf32(fminf(fmaxf(v0, -1.f), 1.f));
                v1 = to_tf32(fminf(fmaxf(v1, -1.f), 1.f));
                v2 = to_tf32(fminf(fmaxf(v2, -1.f), 1.f));
                v3 = to_tf32(fminf(fmaxf(v3, -1.f), 1.f));
            }
            *(float2*)(C + r0 * ldc + cc) = make_float2(v0, v1);
            *(float2*)(C + r1 * ldc + cc) = make_float2(v2, v3);
        }
    }
}

// ---------------- small kernels ----------------
__global__ void bn_prep_kernel(const float* __restrict__ g, const float* __restrict__ b,
                               const float* __restrict__ mu, const float* __restrict__ var,
                               float* __restrict__ sc, float* __restrict__ sh, int n) {
    int i = blockIdx.x * blockDim.x + threadIdx.x;
    if (i < n) {
        float s = g[i] * rsqrtf(var[i] + EPS_);
        sc[i] = s;
        sh[i] = b[i] - mu[i] * s;
    }
}

__global__ void round_copy_kernel(const float* __restrict__ in, float* __restrict__ out, long n) {
    long i = ((long)blockIdx.x * blockDim.x + threadIdx.x) * 4;
    if (i < n) {
        float4 v = *(const float4*)(in + i);
        v.x = to_tf32(v.x); v.y = to_tf32(v.y); v.z = to_tf32(v.z); v.w = to_tf32(v.w);
        *(float4*)(out + i) = v;
    }
}

// V transpose: qkv[b,n][h*1024+512+d] -> vt[(b*8+h)*512+d][n]
__global__ void transpose_v_kernel(const float* __restrict__ qkv, float* __restrict__ vt) {
    __shared__ float t[32][33];
    const int z = blockIdx.z, b = z >> 3, h = z & 7;
    const long n0 = (long)blockIdx.x * 32, d0 = (long)blockIdx.y * 32;
    const int tx = threadIdx.x, ty = threadIdx.y;
    const float* src = qkv + (long)b * N_ * QKVC + (long)h * 1024 + 512;
#pragma unroll
    for (int i = 0; i < 32; i += 8)
        t[ty + i][tx] = src[(n0 + ty + i) * QKVC + d0 + tx];
    __syncthreads();
    float* dst = vt + ((long)z * VD_ + d0) * N_ + n0;
#pragma unroll
    for (int i = 0; i < 32; i += 8)
        dst[(ty + i) * (long)N_ + tx] = t[tx][ty + i];
}

// rowwise softmax over 1024, outputs tf32-rounded (fed into mma)
__global__ void softmax1024_kernel(float* __restrict__ attn) {
    float* p = attn + (long)blockIdx.x * 1024;
    const int t = threadIdx.x;
    float4 a = ((const float4*)p)[t];
    float4 b = ((const float4*)p)[t + 128];

    float m = fmaxf(fmaxf(fmaxf(a.x, a.y), fmaxf(a.z, a.w)),
                    fmaxf(fmaxf(b.x, b.y), fmaxf(b.z, b.w)));
#pragma unroll
    for (int o = 16; o > 0; o >>= 1) m = fmaxf(m, __shfl_xor_sync(0xffffffffu, m, o));
    __shared__ float sm_[4], ss[4];
    if ((t & 31) == 0) sm_[t >> 5] = m;
    __syncthreads();
    m = fmaxf(fmaxf(sm_[0], sm_[1]), fmaxf(sm_[2], sm_[3]));

    a.x = __expf(a.x - m); a.y = __expf(a.y - m); a.z = __expf(a.z - m); a.w = __expf(a.w - m);
    b.x = __expf(b.x - m); b.y = __expf(b.y - m); b.z = __expf(b.z - m); b.w = __expf(b.w - m);

    float s = a.x + a.y + a.z + a.w + b.x + b.y + b.z + b.w;
#pragma unroll
    for (int o = 16; o > 0; o >>= 1) s += __shfl_xor_sync(0xffffffffu, s, o);
    if ((t & 31) == 0) ss[t >> 5] = s;
    __syncthreads();
    s = ss[0] + ss[1] + ss[2] + ss[3];
    const float inv = 1.0f / s;

    a.x = to_tf32(a.x * inv); a.y = to_tf32(a.y * inv);
    a.z = to_tf32(a.z * inv); a.w = to_tf32(a.w * inv);
    b.x = to_tf32(b.x * inv); b.y = to_tf32(b.y * inv);
    b.z = to_tf32(b.z * inv); b.w = to_tf32(b.w * inv);
    ((float4*)p)[t] = a;
    ((float4*)p)[t + 128] = b;
}

// ---------------- launch ----------------
extern "C" void kernel_launch(void* const* d_in, const int* in_sizes, int n_in,
                              void* d_out, int out_size) {
    const float* x          = (const float*)d_in[0];
    const float* qkv_w      = (const float*)d_in[1];
    const float* qkv_gamma  = (const float*)d_in[2];
    const float* qkv_beta   = (const float*)d_in[3];
    const float* qkv_mean   = (const float*)d_in[4];
    const float* qkv_var    = (const float*)d_in[5];
    const float* pos_bias   = (const float*)d_in[6];
    const float* proj_w     = (const float*)d_in[7];
    const float* proj_gamma = (const float*)d_in[8];
    const float* proj_beta  = (const float*)d_in[9];
    const float* proj_mean  = (const float*)d_in[10];
    const float* proj_var   = (const float*)d_in[11];
    float* out = (float*)d_out;

    float *qkv, *attn, *ao, *vt, *xr, *wr, *pwr, *qs, *qh, *ps, *ph;
    cudaGetSymbolAddress((void**)&qkv,  g_qkv);
    cudaGetSymbolAddress((void**)&attn, g_attn);
    cudaGetSymbolAddress((void**)&ao,   g_ao);
    cudaGetSymbolAddress((void**)&vt,   g_vt);
    cudaGetSymbolAddress((void**)&xr,   g_xr);
    cudaGetSymbolAddress((void**)&wr,   g_wr);
    cudaGetSymbolAddress((void**)&pwr,  g_pwr);
    cudaGetSymbolAddress((void**)&qs,   g_qs);
    cudaGetSymbolAddress((void**)&qh,   g_qh);
    cudaGetSymbolAddress((void**)&ps,   g_ps);
    cudaGetSymbolAddress((void**)&ph,   g_ph);

    cudaFuncSetAttribute(mma_gemm_kernel<0>, cudaFuncAttributeMaxDynamicSharedMemorySize, SMEM_BYTES);
    cudaFuncSetAttribute(mma_gemm_kernel<1>, cudaFuncAttributeMaxDynamicSharedMemorySize, SMEM_BYTES);
    cudaFuncSetAttribute(mma_gemm_kernel<2>, cudaFuncAttributeMaxDynamicSharedMemorySize, SMEM_BYTES);
    cudaFuncSetAttribute(mma_gemm_kernel<3>, cudaFuncAttributeMaxDynamicSharedMemorySize, SMEM_BYTES);

    bn_prep_kernel<<<(int)((QKVC + 255) / 256), 256>>>(qkv_gamma, qkv_beta, qkv_mean, qkv_var, qs, qh, (int)QKVC);
    bn_prep_kernel<<<(DOUT + 255) / 256, 256>>>(proj_gamma, proj_beta, proj_mean, proj_var, ps, ph, DOUT);

    // tf32-round inputs that feed MMAs
    round_copy_kernel<<<(int)((MTOK * CIN / 4 + 255) / 256), 256>>>(x, xr, MTOK * CIN);
    round_copy_kernel<<<(int)((QKVC * CIN / 4 + 255) / 256), 256>>>(qkv_w, wr, QKVC * CIN);
    round_copy_kernel<<<(int)(((long)DOUT * NHV / 4 + 255) / 256), 256>>>(proj_w, pwr, (long)DOUT * NHV);

    const long perB = (long)N_ * QKVC;
    const long NN   = (long)N_ * N_;

    // 1) qkv = round(BN(x @ qkv_w^T))   [16384 x 8192], K=768
    mma_gemm_kernel<0><<<dim3(QKVC / 128, MTOK / 128, 1), 256, SMEM_BYTES>>>(
        xr, CIN, 0, 0,
        wr, CIN, 0, 0,
        qkv, QKVC, 0, 0,
        CIN, 1, qs, qh, 0.f, 0, 0);

    // 1b) V transpose
    transpose_v_kernel<<<dim3(N_ / 32, VD_ / 32, B_ * H_), dim3(32, 8)>>>(qkv, vt);

    // 2) logits = q @ k^T * SCALE + pos_bias[h]   per (b,h): [1024 x 1024], K=256
    mma_gemm_kernel<1><<<dim3(N_ / 128, N_ / 128, B_ * H_), 256, SMEM_BYTES>>>(
        qkv,       QKVC, perB, 1024,
        qkv + 256, QKVC, perB, 1024,
        attn, N_, 8 * NN, NN,
        KQ_, H_, pos_bias, nullptr, SCALE_, NN, N_);

    // 3) softmax rows (rounds output)
    softmax1024_kernel<<<(unsigned)(B_ * H_ * N_), 128>>>(attn);

    // 4) ao = round(clip(attn @ vt^T)) per (b,h): [1024 x 512], K=1024
    mma_gemm_kernel<2><<<dim3(VD_ / 128, N_ / 128, B_ * H_), 256, SMEM_BYTES>>>(
        attn, N_, 8 * NN, NN,
        vt, N_, 8L * VD_ * N_, (long)VD_ * N_,
        ao, NHV, (long)N_ * NHV, VD_,
        N_, H_, nullptr, nullptr, 0.f, 0, 0);

    // 5) out = BN(ao @ proj_w^T)   [16384 x 512], K=4096
    mma_gemm_kernel<3><<<dim3(DOUT / 128, MTOK / 128, 1), 256, SMEM_BYTES>>>(
        ao, NHV, 0, 0,
        pwr, NHV, 0, 0,
        out, DOUT, 0, 0,
        (int)NHV, 1, ps, ph, 0.f, 0, 0);
}